// round 4
// baseline (speedup 1.0000x reference)
#include <cuda_runtime.h>
#include <cuda_bf16.h>

// Problem constants: B=4, T=32 -> BT=128 slices; N=512 nodes; F_in=D=128.
#define BT    128
#define NN    512
#define DD    128
#define NROWS (BT * NN)       // 65536 total node-rows

// Scratch (allocation-free: __device__ globals)
__device__ __align__(16) float g_Wh[NROWS * DD];   // 33.5 MB
__device__ float g_es[NROWS], g_ed[NROWS];
__device__ float g_F[NROWS], g_f[NROWS];           // exp(es), exp(0.2*es)
__device__ float g_G[NROWS], g_g[NROWS];           // exp(ed), exp(0.2*ed)
__device__ unsigned g_adjbits[NN * 16];            // bit j%32 of word [i][j/32]

// ---------------------------------------------------------------------------
// Kernel 1: Wh = h @ W   (M=65536, K=128, N=128), tile 64 rows x 128 cols
// ---------------------------------------------------------------------------
__global__ __launch_bounds__(256) void k_gemm(const float* __restrict__ h,
                                              const float* __restrict__ W) {
    __shared__ float hs[64][33];     // +1 pad
    __shared__ float Ws[32][128];
    const int row0 = blockIdx.x * 64;
    const int tid  = threadIdx.x;
    const int tx   = tid & 15;       // col group (8 cols)
    const int ty   = tid >> 4;       // row group (4 rows, stride 16)

    float acc[4][8];
#pragma unroll
    for (int r = 0; r < 4; r++)
#pragma unroll
        for (int d = 0; d < 8; d++) acc[r][d] = 0.f;

    for (int k0 = 0; k0 < 128; k0 += 32) {
        __syncthreads();
#pragma unroll
        for (int l = 0; l < 8; l++) {          // 64x32 = 2048 elems
            int idx = tid + l * 256;
            int r = idx >> 5, k = idx & 31;
            hs[r][k] = h[(size_t)(row0 + r) * 128 + k0 + k];
        }
#pragma unroll
        for (int l = 0; l < 16; l++) {         // 32x128 = 4096 elems
            int idx = tid + l * 256;
            int kk = idx >> 7, d = idx & 127;
            Ws[kk][d] = W[(k0 + kk) * 128 + d];
        }
        __syncthreads();
#pragma unroll
        for (int k = 0; k < 32; k++) {
            float wv[8];
#pragma unroll
            for (int d = 0; d < 8; d++) wv[d] = Ws[k][tx * 8 + d];
#pragma unroll
            for (int r = 0; r < 4; r++) {
                float hv = hs[ty + r * 16][k];
#pragma unroll
                for (int d = 0; d < 8; d++) acc[r][d] += hv * wv[d];
            }
        }
    }
#pragma unroll
    for (int r = 0; r < 4; r++) {
        int row = row0 + ty + r * 16;
#pragma unroll
        for (int d = 0; d < 8; d++)
            g_Wh[(size_t)row * 128 + tx * 8 + d] = acc[r][d];
    }
}

// ---------------------------------------------------------------------------
// Kernel 2: adjacency -> bitmask (adj shared across all bt slices)
// ---------------------------------------------------------------------------
__global__ __launch_bounds__(256) void k_adjbits(const int* __restrict__ adj) {
    int idx = blockIdx.x * 256 + threadIdx.x;   // 8192 words
    int i = idx >> 4, w = idx & 15;
    unsigned bits = 0;
#pragma unroll
    for (int b = 0; b < 32; b++)
        if (adj[i * NN + w * 32 + b] > 0) bits |= (1u << b);
    g_adjbits[idx] = bits;
}

// ---------------------------------------------------------------------------
// Kernel 3: per-node es/ed and exp tables (warp per node)
// ---------------------------------------------------------------------------
__global__ __launch_bounds__(256) void k_prep(const float* __restrict__ a) {
    int warp = (blockIdx.x * 256 + threadIdx.x) >> 5;   // node id, 65536 total
    int lane = threadIdx.x & 31;
    const float* wh = g_Wh + (size_t)warp * 128;
    float s = 0.f, d = 0.f;
#pragma unroll
    for (int l = 0; l < 4; l++) {
        float v = wh[lane + l * 32];
        s += v * a[lane + l * 32];
        d += v * a[128 + lane + l * 32];
    }
#pragma unroll
    for (int off = 16; off > 0; off >>= 1) {
        s += __shfl_down_sync(0xffffffffu, s, off);
        d += __shfl_down_sync(0xffffffffu, d, off);
    }
    if (lane == 0) {
        g_es[warp] = s;  g_ed[warp] = d;
        g_F[warp] = expf(s);        g_f[warp] = expf(0.2f * s);
        g_G[warp] = expf(d);        g_g[warp] = expf(0.2f * d);
    }
}

// ---------------------------------------------------------------------------
// Kernel 4: fused masked-softmax-attention @ Wh.
// Separable exp: c_ij = adj_ij * ((es_i+ed_j > 0) ? F_i*G_j : f_i*g_j)
// out_i = (sum_j c_ij * Wh_j) / (sum_j c_ij)
// Block: one bt slice x 64 rows; 256 threads; thread = 4 rows x 8 cols.
// ---------------------------------------------------------------------------
__global__ __launch_bounds__(256) void k_attn(float* __restrict__ out) {
    __shared__ float Whs[64][128];              // 32 KB j-chunk of Wh
    __shared__ float eds[64], Gs[64], gs[64];

    const int bt   = blockIdx.x >> 3;
    const int tile = blockIdx.x & 7;
    const int base = bt * NN;
    const int i0   = tile * 64;
    const int tid  = threadIdx.x;
    const int tx   = tid & 15;
    const int ty   = tid >> 4;

    float es[4], F[4], f[4], den[4];
    float acc[4][8];
    int rows[4];
#pragma unroll
    for (int r = 0; r < 4; r++) {
        rows[r] = i0 + ty + r * 16;
        int n = base + rows[r];
        es[r] = g_es[n]; F[r] = g_F[n]; f[r] = g_f[n];
        den[r] = 0.f;
#pragma unroll
        for (int d = 0; d < 8; d++) acc[r][d] = 0.f;
    }

    for (int j0 = 0; j0 < NN; j0 += 64) {
        __syncthreads();
        {   // load 64x128 Wh chunk as float4 (2048 float4, 8/thread)
            const float4* src = (const float4*)(g_Wh + (size_t)(base + j0) * 128);
            float4* dst = (float4*)&Whs[0][0];
#pragma unroll
            for (int l = 0; l < 8; l++) dst[tid + l * 256] = src[tid + l * 256];
        }
        if (tid < 64) {
            int n = base + j0 + tid;
            eds[tid] = g_ed[n]; Gs[tid] = g_G[n]; gs[tid] = g_g[n];
        }
        __syncthreads();

        // adjacency bits for this chunk (4 rows x 2 words)
        const int w = j0 >> 5;
        unsigned b0[4], b1[4];
#pragma unroll
        for (int r = 0; r < 4; r++) {
            b0[r] = g_adjbits[rows[r] * 16 + w];
            b1[r] = g_adjbits[rows[r] * 16 + w + 1];
        }

#pragma unroll
        for (int half = 0; half < 2; half++) {
            unsigned bb[4];
#pragma unroll
            for (int r = 0; r < 4; r++) bb[r] = half ? b1[r] : b0[r];
#pragma unroll 8
            for (int jj2 = 0; jj2 < 32; jj2++) {
                int jj = half * 32 + jj2;
                float edv = eds[jj], Gv = Gs[jj], gv = gs[jj];
                const float4* wrow = (const float4*)&Whs[jj][tx * 8];
                float4 w0 = wrow[0], w1 = wrow[1];
#pragma unroll
                for (int r = 0; r < 4; r++) {
                    float t = es[r] + edv;
                    float c = (t > 0.f) ? (F[r] * Gv) : (f[r] * gv);
                    c = ((bb[r] >> jj2) & 1u) ? c : 0.f;
                    den[r] += c;
                    acc[r][0] += c * w0.x; acc[r][1] += c * w0.y;
                    acc[r][2] += c * w0.z; acc[r][3] += c * w0.w;
                    acc[r][4] += c * w1.x; acc[r][5] += c * w1.y;
                    acc[r][6] += c * w1.z; acc[r][7] += c * w1.w;
                }
            }
        }
    }

#pragma unroll
    for (int r = 0; r < 4; r++) {
        float inv = 1.0f / den[r];
        float* o = out + (size_t)(base + rows[r]) * 128 + tx * 8;
#pragma unroll
        for (int d = 0; d < 8; d++) o[d] = acc[r][d] * inv;
    }
}

// ---------------------------------------------------------------------------
extern "C" void kernel_launch(void* const* d_in, const int* in_sizes, int n_in,
                              void* d_out, int out_size) {
    const float* h   = (const float*)d_in[0];   // (4,32,512,128) f32
    const int*   adj = (const int*)d_in[1];     // (512,512) i32
    const float* W   = (const float*)d_in[2];   // (128,128) f32
    const float* a   = (const float*)d_in[3];   // (256,) f32
    float* out = (float*)d_out;                 // (4,32,512,128) f32

    k_gemm<<<NROWS / 64, 256>>>(h, W);      // Wh
    k_adjbits<<<(NN * 16) / 256, 256>>>(adj);
    k_prep<<<NROWS / 8, 256>>>(a);          // es/ed + exp tables (needs Wh)
    k_attn<<<BT * 8, 256>>>(out);           // fused softmax-attention
}